// round 16
// baseline (speedup 1.0000x reference)
#include <cuda_runtime.h>
#include <cuda_fp16.h>
#include <math.h>
#include <stdint.h>

#define BATCH 32
#define LSEQ  2000
#define DIM   1024
#define KEEP  500
#define MROWS (BATCH*KEEP)           // 16000
#define NMASK (BATCH*(LSEQ-KEEP))    // 48000
#define LN_EPS 1e-5f
#define BSCALE 64.0f
#define INV_BSCALE 0.015625f

// GEMM tiling: CTA 128x128, 8 warps of 32x64, KC=64, 3 stages, 2 CTAs/SM
#define MT 128
#define NT 128
#define KC 64
#define NSTAGE (DIM/KC)              // 16
#define NTILES ((MROWS/MT)*(DIM/NT)) // 1000
#define ROWB 144                     // 64 halfs (128B) + 16B pad
#define SPL (128*ROWB)               // 18432
#define STAGE_B (2*SPL)              // 36864 (A,B)
#define SMEM_TOTAL (3*STAGE_B + 16)  // +16 for tile-steal slot
#define GEMM_GRID 296                // persistent + work stealing

// -------- scratch (device globals) --------
__device__ int   g_rank[BATCH*LSEQ];
__device__ int   g_keep[BATCH*KEEP];
__device__ unsigned g_tilectr;
__device__ __align__(16) __half g_Ah[MROWS*DIM];
__device__ __align__(16) __half g_Bh[DIM*DIM];   // [n][k] = 64*W_dec[k][n] (fp16)
__device__ __align__(16) float g_gw[DIM];        // gamma2*W_pred
__device__ float g_consts[2];                    // {sum(g2*Wp), sum(be2*Wp)+bp}
__device__ float g_part[3*8*MROWS];              // [stat][ntile][row]
__device__ float g_s[MROWS+1];
__device__ float g_losspart[256];

// =============================== PTX helpers ===============================
__device__ __forceinline__ uint32_t s2u(const void* p) {
    uint32_t a;
    asm("{ .reg .u64 t; cvta.to.shared.u64 t, %1; cvt.u32.u64 %0, t; }" : "=r"(a) : "l"(p));
    return a;
}
__device__ __forceinline__ void cp16(uint32_t s, const void* g) {
    asm volatile("cp.async.cg.shared.global [%0], [%1], 16;" :: "r"(s), "l"(g) : "memory");
}
__device__ __forceinline__ void ldm4(uint32_t* r, uint32_t addr) {
    asm volatile("ldmatrix.sync.aligned.m8n8.x4.shared.b16 {%0,%1,%2,%3}, [%4];"
                 : "=r"(r[0]), "=r"(r[1]), "=r"(r[2]), "=r"(r[3]) : "r"(addr));
}
__device__ __forceinline__ void mma16816(float* c, const uint32_t* a, const uint32_t* b) {
    asm volatile(
        "mma.sync.aligned.m16n8k16.row.col.f32.f16.f16.f32 "
        "{%0,%1,%2,%3}, {%4,%5,%6,%7}, {%8,%9}, {%0,%1,%2,%3};"
        : "+f"(c[0]), "+f"(c[1]), "+f"(c[2]), "+f"(c[3])
        : "r"(a[0]), "r"(a[1]), "r"(a[2]), "r"(a[3]), "r"(b[0]), "r"(b[1]));
}

// ===== Kernel 1 (fused setup): rank (256 blocks) + prep_b (1024) + consts (1) =====
__global__ void setup_kernel(const float* __restrict__ noise,
                             const float* __restrict__ Wd,
                             const float* __restrict__ g2,
                             const float* __restrict__ be2,
                             const float* __restrict__ Wp,
                             const float* __restrict__ bp)
{
    __shared__ float sh[LSEQ];
    const int bid = blockIdx.x, tid = threadIdx.x;

    if (bid < 256) {
        const int b = bid >> 3, seg = bid & 7;
        const float* nrow = noise + b*LSEQ;
        for (int i = tid; i < LSEQ; i += 256) sh[i] = nrow[i];
        __syncthreads();
        const int j = seg*250 + tid;
        if (tid >= 250) return;
        const float nj = sh[j];
        int r = 0;
        #pragma unroll 4
        for (int k = 0; k < LSEQ; ++k) {
            float nk = sh[k];
            r += (nk < nj) || (nk == nj && k < j);
        }
        g_rank[b*LSEQ + j] = r;
        if (r < KEEP) g_keep[b*KEEP + r] = j;
    } else if (bid < 1280) {
        const int bb = bid - 256, bx = bb & 31, by = bb >> 5;
        float (*t)[33] = (float(*)[33])sh;
        const int tx = tid & 31, ty = tid >> 5;
        #pragma unroll
        for (int j = 0; j < 32; j += 8)
            t[ty+j][tx] = Wd[(size_t)(by*32 + ty + j)*DIM + bx*32 + tx];
        __syncthreads();
        #pragma unroll
        for (int j = 0; j < 32; j += 8) {
            float v = t[tx][ty+j] * BSCALE;
            size_t o = (size_t)(bx*32 + ty + j)*DIM + by*32 + tx;  // [n][k]
            g_Bh[o] = __float2half_rn(v);
        }
    } else {
        if (tid == 0) g_tilectr = GEMM_GRID;   // reset tile-steal counter
        float sg = 0.f, sb = 0.f;
        #pragma unroll
        for (int i = 0; i < 4; ++i) {
            int d = tid + i*256;
            float w = Wp[d];
            float gv = g2[d]*w;
            g_gw[d] = gv;
            sg += gv;
            sb += be2[d]*w;
        }
        float* r1 = sh; float* r2 = sh + 256;
        r1[tid] = sg; r2[tid] = sb; __syncthreads();
        #pragma unroll
        for (int o = 128; o > 0; o >>= 1) {
            if (tid < o) { r1[tid] += r1[tid+o]; r2[tid] += r2[tid+o]; }
            __syncthreads();
        }
        if (tid == 0) { g_consts[0] = r1[0]; g_consts[1] = r2[0] + bp[0]; }
    }
}

// ===== Kernel 2: gather + encode + LN1 -> fp16 A (+latent0), warp/row =====
__global__ void enc_ln_kernel(const float* __restrict__ expr,
                              const int*   __restrict__ idx,
                              const float* __restrict__ pos,
                              const float* __restrict__ cls,
                              const float* __restrict__ w_enc,
                              const float* __restrict__ b_enc,
                              const float* __restrict__ g1,
                              const float* __restrict__ be1,
                              float* __restrict__ out_lat0)
{
    const int g = blockIdx.x*8 + (threadIdx.x >> 5);   // 0..16031
    const int lane = threadIdx.x & 31;
    const int b = g / (KEEP+1);
    const int tt = g - b*(KEEP+1);                     // 0 = cls row

    float4 v[8];
    if (tt == 0) {
        #pragma unroll
        for (int i = 0; i < 8; ++i) {
            const int e4 = lane + i*32;
            float4 c = ((const float4*)cls)[e4];
            float4 p = ((const float4*)pos)[e4];
            v[i].x = c.x + p.x; v[i].y = c.y + p.y;
            v[i].z = c.z + p.z; v[i].w = c.w + p.w;
        }
    } else {
        const int j = g_keep[b*KEEP + tt - 1];
        const float e = expr[b*LSEQ + j];
        const float* prow = pos + (size_t)idx[b*LSEQ + j]*DIM;
        #pragma unroll
        for (int i = 0; i < 8; ++i) {
            const int e4 = lane + i*32;
            float4 p  = ((const float4*)prow)[e4];
            float4 w  = ((const float4*)w_enc)[e4];
            float4 bb = ((const float4*)b_enc)[e4];
            v[i].x = fmaf(e, w.x, bb.x) + p.x;
            v[i].y = fmaf(e, w.y, bb.y) + p.y;
            v[i].z = fmaf(e, w.z, bb.z) + p.z;
            v[i].w = fmaf(e, w.w, bb.w) + p.w;
        }
    }

    float s = 0.f, sq = 0.f;
    #pragma unroll
    for (int i = 0; i < 8; ++i) {
        s  += v[i].x + v[i].y + v[i].z + v[i].w;
        sq += v[i].x*v[i].x + v[i].y*v[i].y + v[i].z*v[i].z + v[i].w*v[i].w;
    }
    #pragma unroll
    for (int o = 16; o; o >>= 1) {
        s  += __shfl_xor_sync(0xFFFFFFFFu, s,  o);
        sq += __shfl_xor_sync(0xFFFFFFFFu, sq, o);
    }
    const float mean = s * (1.0f/DIM);
    const float var  = sq * (1.0f/DIM) - mean*mean;
    const float inv  = rsqrtf(var + LN_EPS);

    if (tt == 0) {
        float* dst = out_lat0 + b*DIM;
        #pragma unroll
        for (int i = 0; i < 8; ++i) {
            const int e4 = lane + i*32;
            const float4 gg = ((const float4*)g1)[e4];
            const float4 be = ((const float4*)be1)[e4];
            dst[e4*4+0] = (v[i].x - mean)*inv*gg.x + be.x;
            dst[e4*4+1] = (v[i].y - mean)*inv*gg.y + be.y;
            dst[e4*4+2] = (v[i].z - mean)*inv*gg.z + be.z;
            dst[e4*4+3] = (v[i].w - mean)*inv*gg.w + be.w;
        }
    } else {
        const size_t row = (size_t)(b*KEEP + tt - 1)*DIM;
        #pragma unroll
        for (int i = 0; i < 8; ++i) {
            const int e4 = lane + i*32;
            const float4 gg = ((const float4*)g1)[e4];
            const float4 be = ((const float4*)be1)[e4];
            float r0 = (v[i].x - mean)*inv*gg.x + be.x;
            float r1 = (v[i].y - mean)*inv*gg.y + be.y;
            float r2 = (v[i].z - mean)*inv*gg.z + be.z;
            float r3 = (v[i].w - mean)*inv*gg.w + be.w;
            ((__half2*)(g_Ah + row))[e4*2+0] = __floats2half2_rn(r0, r1);
            ((__half2*)(g_Ah + row))[e4*2+1] = __floats2half2_rn(r2, r3);
        }
    }
}

// ====== Kernel 3: fp16 GEMM, 8 warps of 32x64, KC=64, 3-stage, tile stealing ======
__device__ __forceinline__ void load_stage(uint32_t sb, int stage, int bm, int bn, int tid)
{
    const uint32_t st = sb + (uint32_t)(stage % 3) * STAGE_B;
    const int kbase = stage * KC;
    #pragma unroll
    for (int i = 0; i < 8; ++i) {
        const int id = i*256 + tid;           // 0..2047
        const __half* src;
        uint32_t dst;
        if (id < 1024) {                      // A: 128 rows x 8 segs
            const int r = id >> 3, seg = id & 7;
            src = g_Ah + (size_t)(bm + r)*DIM + kbase + seg*8;
            dst = st + (uint32_t)(r*ROWB + seg*16);
        } else {                              // B: 128 rows x 8 segs
            const int t = id - 1024;
            const int r = t >> 3, seg = t & 7;
            src = g_Bh + (size_t)(bn + r)*DIM + kbase + seg*8;
            dst = st + (uint32_t)(SPL + r*ROWB + seg*16);
        }
        cp16(dst, src);
    }
    asm volatile("cp.async.commit_group;" ::: "memory");
}

__global__ void __launch_bounds__(256, 2)
gemm_tc_kernel(const float* __restrict__ bias)
{
    extern __shared__ char sm_[];
    const uint32_t sb = s2u(sm_);
    int* steal = (int*)(sm_ + 3*STAGE_B);
    const int tid = threadIdx.x, wid = tid >> 5, lane = tid & 31;
    const int wm = wid & 3, wn = wid >> 2;     // 4 M-groups (32) x 2 N-groups (64)

    const uint32_t aOff = (uint32_t)((wm*32 + (lane & 15))*ROWB + (lane >> 4)*16);
    const uint32_t bOff = (uint32_t)(SPL
                       + (wn*64 + (lane & 7) + (lane >> 4)*8)*ROWB
                       + ((lane >> 3) & 1)*16);
    const int c2 = (lane & 3)*2;
    const int r4 = lane >> 2;

    uint32_t Ah[2][4], Bh[4][4];

    int tile = blockIdx.x;
    while (tile < NTILES) {
        const int bn = (tile & 7) * NT;
        const int bm = (tile >> 3) * MT;

        float acc[2][8][4] = {};
        load_stage(sb, 0, bm, bn, tid);
        load_stage(sb, 1, bm, bn, tid);
        load_stage(sb, 2, bm, bn, tid);
        asm volatile("cp.async.wait_group 2;" ::: "memory");
        __syncthreads();

        // preload ks0 frags of stage 0
        #pragma unroll
        for (int mi = 0; mi < 2; ++mi)
            ldm4(Ah[mi], sb + aOff + (uint32_t)(mi*16*ROWB));
        #pragma unroll
        for (int np = 0; np < 4; ++np)
            ldm4(Bh[np], sb + bOff + (uint32_t)(np*16*ROWB));

        for (int s = 0; s < NSTAGE; ++s) {
            const uint32_t st = sb + (uint32_t)(s % 3) * STAGE_B;

            #pragma unroll
            for (int ks = 0; ks < 3; ++ks) {
                #pragma unroll
                for (int mi = 0; mi < 2; ++mi)
                    #pragma unroll
                    for (int ni = 0; ni < 8; ++ni)
                        mma16816(acc[mi][ni], Ah[mi], &Bh[ni>>1][(ni&1)*2]);
                const uint32_t kb = (uint32_t)((ks+1)*32);
                #pragma unroll
                for (int mi = 0; mi < 2; ++mi)
                    ldm4(Ah[mi], st + aOff + (uint32_t)(mi*16*ROWB) + kb);
                #pragma unroll
                for (int np = 0; np < 4; ++np)
                    ldm4(Bh[np], st + bOff + (uint32_t)(np*16*ROWB) + kb);
            }
            #pragma unroll
            for (int mi = 0; mi < 2; ++mi)
                #pragma unroll
                for (int ni = 0; ni < 8; ++ni)
                    mma16816(acc[mi][ni], Ah[mi], &Bh[ni>>1][(ni&1)*2]);

            if (s + 1 < NSTAGE) {
                if (s + 3 < NSTAGE)
                    asm volatile("cp.async.wait_group 1;" ::: "memory");
                else
                    asm volatile("cp.async.wait_group 0;" ::: "memory");
                __syncthreads();
                const uint32_t sn = sb + (uint32_t)((s+1) % 3) * STAGE_B;
                #pragma unroll
                for (int mi = 0; mi < 2; ++mi)
                    ldm4(Ah[mi], sn + aOff + (uint32_t)(mi*16*ROWB));
                #pragma unroll
                for (int np = 0; np < 4; ++np)
                    ldm4(Bh[np], sn + bOff + (uint32_t)(np*16*ROWB));
                if (s + 3 < NSTAGE) load_stage(sb, s + 3, bm, bn, tid);
            }
        }

        // ---- fused epilogue: per-row partial S1,S2,S3 over this CTA's 128 cols ----
        __syncthreads();
        float* sred = (float*)sm_;             // [2 wn][128 rows][3]

        float st1[2][2] = {}, st2[2][2] = {}, st3[2][2] = {};
        #pragma unroll
        for (int ni = 0; ni < 8; ++ni) {
            const int n = bn + wn*64 + ni*8 + c2;
            const float2 bv = *(const float2*)(bias + n);
            const float2 gv = *(const float2*)(g_gw + n);
            #pragma unroll
            for (int mi = 0; mi < 2; ++mi) {
                float x0 = acc[mi][ni][0]*INV_BSCALE + bv.x;
                float x1 = acc[mi][ni][1]*INV_BSCALE + bv.y;
                float x2 = acc[mi][ni][2]*INV_BSCALE + bv.x;
                float x3 = acc[mi][ni][3]*INV_BSCALE + bv.y;
                st1[mi][0] += x0 + x1;           st1[mi][1] += x2 + x3;
                st2[mi][0] += x0*x0 + x1*x1;     st2[mi][1] += x2*x2 + x3*x3;
                st3[mi][0] += x0*gv.x + x1*gv.y; st3[mi][1] += x2*gv.x + x3*gv.y;
            }
        }
        #pragma unroll
        for (int mi = 0; mi < 2; ++mi)
            #pragma unroll
            for (int h = 0; h < 2; ++h) {
                #pragma unroll
                for (int o = 1; o < 4; o <<= 1) {
                    st1[mi][h] += __shfl_xor_sync(0xFFFFFFFFu, st1[mi][h], o);
                    st2[mi][h] += __shfl_xor_sync(0xFFFFFFFFu, st2[mi][h], o);
                    st3[mi][h] += __shfl_xor_sync(0xFFFFFFFFu, st3[mi][h], o);
                }
            }
        if ((lane & 3) == 0) {
            #pragma unroll
            for (int mi = 0; mi < 2; ++mi)
                #pragma unroll
                for (int h = 0; h < 2; ++h) {
                    const int row = wm*32 + mi*16 + h*8 + r4;
                    float* p = sred + (wn*128 + row)*3;
                    p[0] = st1[mi][h]; p[1] = st2[mi][h]; p[2] = st3[mi][h];
                }
        }
        __syncthreads();
        if (tid < 128) {
            const int m = bm + tid;
            const int t8 = tile & 7;
            #pragma unroll
            for (int c = 0; c < 3; ++c)
                g_part[(c*8 + t8)*MROWS + m] =
                    sred[(0*128 + tid)*3 + c] + sred[(1*128 + tid)*3 + c];
        }
        // ---- steal next tile ----
        if (tid == 0) *steal = (int)atomicAdd(&g_tilectr, 1u);
        __syncthreads();
        tile = *steal;
    }
}

// ===== Kernel 4: combine partials -> g_s (125 blocks) + mask pred (block 125) =====
__global__ void combine_kernel(const float* __restrict__ mask_token)
{
    const int tid = threadIdx.x;
    if (blockIdx.x < 125) {
        const int m = blockIdx.x*128 + tid;
        float S1 = 0.f, S2 = 0.f, S3 = 0.f;
        #pragma unroll
        for (int t = 0; t < 8; ++t) {
            S1 += g_part[(0*8 + t)*MROWS + m];
            S2 += g_part[(1*8 + t)*MROWS + m];
            S3 += g_part[(2*8 + t)*MROWS + m];
        }
        const float mean = S1 * (1.0f/DIM);
        const float var  = S2 * (1.0f/DIM) - mean*mean;
        const float inv  = rsqrtf(var + LN_EPS);
        g_s[m] = inv*(S3 - mean*g_consts[0]) + g_consts[1];
    } else {
        const int lane = tid & 31, wrp = tid >> 5;
        float s1 = 0.f, s2 = 0.f, s3 = 0.f;
        #pragma unroll
        for (int i = 0; i < 8; ++i) {
            const int d = tid + i*128;
            const float x = mask_token[d];
            s1 += x; s2 += x*x; s3 += x*g_gw[d];
        }
        #pragma unroll
        for (int o = 16; o; o >>= 1) {
            s1 += __shfl_xor_sync(0xFFFFFFFFu, s1, o);
            s2 += __shfl_xor_sync(0xFFFFFFFFu, s2, o);
            s3 += __shfl_xor_sync(0xFFFFFFFFu, s3, o);
        }
        __shared__ float ws[12];
        if (lane == 0) { ws[wrp] = s1; ws[4+wrp] = s2; ws[8+wrp] = s3; }
        __syncthreads();
        if (tid == 0) {
            float S1 = ws[0]+ws[1]+ws[2]+ws[3];
            float S2 = ws[4]+ws[5]+ws[6]+ws[7];
            float S3 = ws[8]+ws[9]+ws[10]+ws[11];
            const float mean = S1 * (1.0f/DIM);
            const float var  = S2 * (1.0f/DIM) - mean*mean;
            const float inv  = rsqrtf(var + LN_EPS);
            g_s[MROWS] = inv*(S3 - mean*g_consts[0]) + g_consts[1];
        }
    }
}

// ===== Kernel 5: scatter pred/mask + loss partial, grid (8, 32) =====
__global__ void out_kernel(const float* __restrict__ expr,
                           float* __restrict__ out_pred,
                           float* __restrict__ out_mask)
{
    const int b = blockIdx.y, seg = blockIdx.x, tid = threadIdx.x;
    const float cm = g_s[MROWS];
    float part = 0.f;
    if (tid < 250) {
        const int l = seg*250 + tid;
        const int r = g_rank[b*LSEQ + l];
        const bool masked = (r >= KEEP);
        const float p = masked ? cm : g_s[b*KEEP + r];
        out_pred[b*LSEQ + l] = p;
        out_mask[b*LSEQ + l] = masked ? 1.0f : 0.0f;
        if (masked) {
            float t = expr[b*LSEQ + l];
            if (isnan(t)) t = 0.f;
            const float d = p - t;
            part = d*d;
        }
    }
    __shared__ float red[256];
    red[tid] = part; __syncthreads();
    #pragma unroll
    for (int o = 128; o > 0; o >>= 1) {
        if (tid < o) red[tid] += red[tid+o];
        __syncthreads();
    }
    if (tid == 0) g_losspart[b*8 + seg] = red[0];
}

// ===== Kernel 6: final loss =====
__global__ void loss_kernel(float* __restrict__ out)
{
    const int tid = threadIdx.x;
    __shared__ float red[256];
    red[tid] = g_losspart[tid]; __syncthreads();
    #pragma unroll
    for (int o = 128; o > 0; o >>= 1) {
        if (tid < o) red[tid] += red[tid+o];
        __syncthreads();
    }
    if (tid == 0) out[0] = red[0] / (float)NMASK;
}

// =============================== launch ===============================
extern "C" void kernel_launch(void* const* d_in, const int* in_sizes, int n_in,
                              void* d_out, int out_size)
{
    const float* expr      = (const float*)d_in[0];
    const int*   idx       = (const int*)  d_in[1];
    const float* noise     = (const float*)d_in[2];
    const float* pos_table = (const float*)d_in[3];
    const float* cls_token = (const float*)d_in[4];
    const float* w_enc     = (const float*)d_in[5];
    const float* b_enc     = (const float*)d_in[6];
    const float* gamma1    = (const float*)d_in[7];
    const float* beta1     = (const float*)d_in[8];
    const float* W_dec     = (const float*)d_in[9];
    const float* b_dec     = (const float*)d_in[10];
    const float* mask_tok  = (const float*)d_in[11];
    const float* gamma2    = (const float*)d_in[12];
    const float* beta2     = (const float*)d_in[13];
    const float* W_pred    = (const float*)d_in[14];
    const float* b_pred    = (const float*)d_in[15];

    float* out = (float*)d_out;
    float* out_loss  = out;
    float* out_pred  = out + 1;
    float* out_mask  = out + 1 + BATCH*LSEQ;
    float* out_lat0  = out + 1 + 2*BATCH*LSEQ;

    cudaFuncSetAttribute(gemm_tc_kernel,
                         cudaFuncAttributeMaxDynamicSharedMemorySize, SMEM_TOTAL);

    setup_kernel<<<1281, 256>>>(noise, W_dec, gamma2, beta2, W_pred, b_pred);
    enc_ln_kernel<<<(BATCH*(KEEP+1))/8, 256>>>(expr, idx, pos_table, cls_token,
                                               w_enc, b_enc, gamma1, beta1, out_lat0);
    gemm_tc_kernel<<<GEMM_GRID, 256, SMEM_TOTAL>>>(b_dec);
    combine_kernel<<<126, 128>>>(mask_tok);
    out_kernel<<<dim3(8, BATCH), 256>>>(expr, out_pred, out_mask);
    loss_kernel<<<1, 256>>>(out_loss);
}

// round 17
// speedup vs baseline: 1.0953x; 1.0953x over previous
#include <cuda_runtime.h>
#include <cuda_fp16.h>
#include <math.h>
#include <stdint.h>

#define BATCH 32
#define LSEQ  2000
#define DIM   1024
#define KEEP  500
#define MROWS (BATCH*KEEP)           // 16000
#define NMASK (BATCH*(LSEQ-KEEP))    // 48000
#define LN_EPS 1e-5f
#define BSCALE 64.0f
#define INV_BSCALE 0.015625f

// GEMM tiling: CTA 128x128, 8 warps of 32x64, KC=64, 3 stages, 2 CTAs/SM
#define MT 128
#define NT 128
#define KC 64
#define NSTAGE (DIM/KC)              // 16
#define NTILES ((MROWS/MT)*(DIM/NT)) // 1000
#define ROWB 144                     // 64 halfs (128B) + 16B pad
#define SPL (128*ROWB)               // 18432
#define STAGE_B (2*SPL)              // 36864 (A,B)
#define SMEM_TOTAL (3*STAGE_B)       // 110592
#define GEMM_GRID 296                // persistent (static schedule)

// -------- scratch (device globals) --------
__device__ int   g_rank[BATCH*LSEQ];
__device__ int   g_keep[BATCH*KEEP];
__device__ __align__(16) __half g_Ah[MROWS*DIM];
__device__ __align__(16) __half g_Bh[DIM*DIM];   // [n][k] = 64*W_dec[k][n] (fp16)
__device__ __align__(16) float g_gw[DIM];        // gamma2*W_pred
__device__ float g_consts[2];                    // {sum(g2*Wp), sum(be2*Wp)+bp}
__device__ float g_part[3*8*MROWS];              // [stat][ntile][row]
__device__ float g_s[MROWS+1];
__device__ float g_losspart[256];

// =============================== PTX helpers ===============================
__device__ __forceinline__ uint32_t s2u(const void* p) {
    uint32_t a;
    asm("{ .reg .u64 t; cvta.to.shared.u64 t, %1; cvt.u32.u64 %0, t; }" : "=r"(a) : "l"(p));
    return a;
}
__device__ __forceinline__ void cp16(uint32_t s, const void* g) {
    asm volatile("cp.async.cg.shared.global [%0], [%1], 16;" :: "r"(s), "l"(g) : "memory");
}
__device__ __forceinline__ void ldm4(uint32_t* r, uint32_t addr) {
    asm volatile("ldmatrix.sync.aligned.m8n8.x4.shared.b16 {%0,%1,%2,%3}, [%4];"
                 : "=r"(r[0]), "=r"(r[1]), "=r"(r[2]), "=r"(r[3]) : "r"(addr));
}
__device__ __forceinline__ void mma16816(float* c, const uint32_t* a, const uint32_t* b) {
    asm volatile(
        "mma.sync.aligned.m16n8k16.row.col.f32.f16.f16.f32 "
        "{%0,%1,%2,%3}, {%4,%5,%6,%7}, {%8,%9}, {%0,%1,%2,%3};"
        : "+f"(c[0]), "+f"(c[1]), "+f"(c[2]), "+f"(c[3])
        : "r"(a[0]), "r"(a[1]), "r"(a[2]), "r"(a[3]), "r"(b[0]), "r"(b[1]));
}

// ===== Kernel 1 (fused setup): rank (256 blocks) + prep_b (1024) + consts (1) =====
__global__ void setup_kernel(const float* __restrict__ noise,
                             const float* __restrict__ Wd,
                             const float* __restrict__ g2,
                             const float* __restrict__ be2,
                             const float* __restrict__ Wp,
                             const float* __restrict__ bp)
{
    __shared__ float sh[LSEQ];
    const int bid = blockIdx.x, tid = threadIdx.x;

    if (bid < 256) {
        const int b = bid >> 3, seg = bid & 7;
        const float* nrow = noise + b*LSEQ;
        for (int i = tid; i < LSEQ; i += 256) sh[i] = nrow[i];
        __syncthreads();
        const int j = seg*250 + tid;
        if (tid >= 250) return;
        const float nj = sh[j];
        const float4* sh4 = (const float4*)sh;
        int r = 0;
        #pragma unroll 4
        for (int k4 = 0; k4 < LSEQ/4; ++k4) {
            const float4 nk = sh4[k4];
            const int kb = k4*4;
            r += (nk.x < nj) || (nk.x == nj && kb+0 < j);
            r += (nk.y < nj) || (nk.y == nj && kb+1 < j);
            r += (nk.z < nj) || (nk.z == nj && kb+2 < j);
            r += (nk.w < nj) || (nk.w == nj && kb+3 < j);
        }
        g_rank[b*LSEQ + j] = r;
        if (r < KEEP) g_keep[b*KEEP + r] = j;
    } else if (bid < 1280) {
        const int bb = bid - 256, bx = bb & 31, by = bb >> 5;
        float (*t)[33] = (float(*)[33])sh;
        const int tx = tid & 31, ty = tid >> 5;
        #pragma unroll
        for (int j = 0; j < 32; j += 8)
            t[ty+j][tx] = Wd[(size_t)(by*32 + ty + j)*DIM + bx*32 + tx];
        __syncthreads();
        #pragma unroll
        for (int j = 0; j < 32; j += 8) {
            float v = t[tx][ty+j] * BSCALE;
            size_t o = (size_t)(bx*32 + ty + j)*DIM + by*32 + tx;  // [n][k]
            g_Bh[o] = __float2half_rn(v);
        }
    } else {
        float sg = 0.f, sb = 0.f;
        #pragma unroll
        for (int i = 0; i < 4; ++i) {
            int d = tid + i*256;
            float w = Wp[d];
            float gv = g2[d]*w;
            g_gw[d] = gv;
            sg += gv;
            sb += be2[d]*w;
        }
        float* r1 = sh; float* r2 = sh + 256;
        r1[tid] = sg; r2[tid] = sb; __syncthreads();
        #pragma unroll
        for (int o = 128; o > 0; o >>= 1) {
            if (tid < o) { r1[tid] += r1[tid+o]; r2[tid] += r2[tid+o]; }
            __syncthreads();
        }
        if (tid == 0) { g_consts[0] = r1[0]; g_consts[1] = r2[0] + bp[0]; }
    }
}

// ===== Kernel 2: gather + encode + LN1 -> fp16 A (+latent0), warp/row =====
__global__ void enc_ln_kernel(const float* __restrict__ expr,
                              const int*   __restrict__ idx,
                              const float* __restrict__ pos,
                              const float* __restrict__ cls,
                              const float* __restrict__ w_enc,
                              const float* __restrict__ b_enc,
                              const float* __restrict__ g1,
                              const float* __restrict__ be1,
                              float* __restrict__ out_lat0)
{
    const int g = blockIdx.x*8 + (threadIdx.x >> 5);   // 0..16031
    const int lane = threadIdx.x & 31;
    const int b = g / (KEEP+1);
    const int tt = g - b*(KEEP+1);                     // 0 = cls row

    float4 v[8];
    if (tt == 0) {
        #pragma unroll
        for (int i = 0; i < 8; ++i) {
            const int e4 = lane + i*32;
            float4 c = ((const float4*)cls)[e4];
            float4 p = ((const float4*)pos)[e4];
            v[i].x = c.x + p.x; v[i].y = c.y + p.y;
            v[i].z = c.z + p.z; v[i].w = c.w + p.w;
        }
    } else {
        const int j = g_keep[b*KEEP + tt - 1];
        const float e = expr[b*LSEQ + j];
        const float* prow = pos + (size_t)idx[b*LSEQ + j]*DIM;
        #pragma unroll
        for (int i = 0; i < 8; ++i) {
            const int e4 = lane + i*32;
            float4 p  = ((const float4*)prow)[e4];
            float4 w  = ((const float4*)w_enc)[e4];
            float4 bb = ((const float4*)b_enc)[e4];
            v[i].x = fmaf(e, w.x, bb.x) + p.x;
            v[i].y = fmaf(e, w.y, bb.y) + p.y;
            v[i].z = fmaf(e, w.z, bb.z) + p.z;
            v[i].w = fmaf(e, w.w, bb.w) + p.w;
        }
    }

    float s = 0.f, sq = 0.f;
    #pragma unroll
    for (int i = 0; i < 8; ++i) {
        s  += v[i].x + v[i].y + v[i].z + v[i].w;
        sq += v[i].x*v[i].x + v[i].y*v[i].y + v[i].z*v[i].z + v[i].w*v[i].w;
    }
    #pragma unroll
    for (int o = 16; o; o >>= 1) {
        s  += __shfl_xor_sync(0xFFFFFFFFu, s,  o);
        sq += __shfl_xor_sync(0xFFFFFFFFu, sq, o);
    }
    const float mean = s * (1.0f/DIM);
    const float var  = sq * (1.0f/DIM) - mean*mean;
    const float inv  = rsqrtf(var + LN_EPS);

    if (tt == 0) {
        float* dst = out_lat0 + b*DIM;
        #pragma unroll
        for (int i = 0; i < 8; ++i) {
            const int e4 = lane + i*32;
            const float4 gg = ((const float4*)g1)[e4];
            const float4 be = ((const float4*)be1)[e4];
            dst[e4*4+0] = (v[i].x - mean)*inv*gg.x + be.x;
            dst[e4*4+1] = (v[i].y - mean)*inv*gg.y + be.y;
            dst[e4*4+2] = (v[i].z - mean)*inv*gg.z + be.z;
            dst[e4*4+3] = (v[i].w - mean)*inv*gg.w + be.w;
        }
    } else {
        const size_t row = (size_t)(b*KEEP + tt - 1)*DIM;
        #pragma unroll
        for (int i = 0; i < 8; ++i) {
            const int e4 = lane + i*32;
            const float4 gg = ((const float4*)g1)[e4];
            const float4 be = ((const float4*)be1)[e4];
            float r0 = (v[i].x - mean)*inv*gg.x + be.x;
            float r1 = (v[i].y - mean)*inv*gg.y + be.y;
            float r2 = (v[i].z - mean)*inv*gg.z + be.z;
            float r3 = (v[i].w - mean)*inv*gg.w + be.w;
            ((__half2*)(g_Ah + row))[e4*2+0] = __floats2half2_rn(r0, r1);
            ((__half2*)(g_Ah + row))[e4*2+1] = __floats2half2_rn(r2, r3);
        }
    }
}

// ====== Kernel 3: persistent fp16 GEMM, 8 warps of 32x64, KC=64, 3-stage ======
__device__ __forceinline__ void load_stage(uint32_t sb, int stage, int bm, int bn, int tid)
{
    const uint32_t st = sb + (uint32_t)(stage % 3) * STAGE_B;
    const int kbase = stage * KC;
    #pragma unroll
    for (int i = 0; i < 8; ++i) {
        const int id = i*256 + tid;           // 0..2047
        const __half* src;
        uint32_t dst;
        if (id < 1024) {                      // A: 128 rows x 8 segs
            const int r = id >> 3, seg = id & 7;
            src = g_Ah + (size_t)(bm + r)*DIM + kbase + seg*8;
            dst = st + (uint32_t)(r*ROWB + seg*16);
        } else {                              // B: 128 rows x 8 segs
            const int t = id - 1024;
            const int r = t >> 3, seg = t & 7;
            src = g_Bh + (size_t)(bn + r)*DIM + kbase + seg*8;
            dst = st + (uint32_t)(SPL + r*ROWB + seg*16);
        }
        cp16(dst, src);
    }
    asm volatile("cp.async.commit_group;" ::: "memory");
}

__global__ void __launch_bounds__(256, 2)
gemm_tc_kernel(const float* __restrict__ bias)
{
    extern __shared__ char sm_[];
    const uint32_t sb = s2u(sm_);
    const int tid = threadIdx.x, wid = tid >> 5, lane = tid & 31;
    const int wm = wid & 3, wn = wid >> 2;     // 4 M-groups (32) x 2 N-groups (64)

    const uint32_t aOff = (uint32_t)((wm*32 + (lane & 15))*ROWB + (lane >> 4)*16);
    const uint32_t bOff = (uint32_t)(SPL
                       + (wn*64 + (lane & 7) + (lane >> 4)*8)*ROWB
                       + ((lane >> 3) & 1)*16);
    const int c2 = (lane & 3)*2;
    const int r4 = lane >> 2;

    uint32_t Ah[2][4], Bh[4][4];

    for (int tile = blockIdx.x; tile < NTILES; tile += GEMM_GRID) {
        const int bn = (tile & 7) * NT;
        const int bm = (tile >> 3) * MT;

        float acc[2][8][4] = {};
        __syncthreads();                 // prior tile's epilogue smem reads done
        load_stage(sb, 0, bm, bn, tid);
        load_stage(sb, 1, bm, bn, tid);
        load_stage(sb, 2, bm, bn, tid);
        asm volatile("cp.async.wait_group 2;" ::: "memory");
        __syncthreads();

        // preload ks0 frags of stage 0
        #pragma unroll
        for (int mi = 0; mi < 2; ++mi)
            ldm4(Ah[mi], sb + aOff + (uint32_t)(mi*16*ROWB));
        #pragma unroll
        for (int np = 0; np < 4; ++np)
            ldm4(Bh[np], sb + bOff + (uint32_t)(np*16*ROWB));

        for (int s = 0; s < NSTAGE; ++s) {
            const uint32_t st = sb + (uint32_t)(s % 3) * STAGE_B;

            #pragma unroll
            for (int ks = 0; ks < 3; ++ks) {
                #pragma unroll
                for (int mi = 0; mi < 2; ++mi)
                    #pragma unroll
                    for (int ni = 0; ni < 8; ++ni)
                        mma16816(acc[mi][ni], Ah[mi], &Bh[ni>>1][(ni&1)*2]);
                const uint32_t kb = (uint32_t)((ks+1)*32);
                #pragma unroll
                for (int mi = 0; mi < 2; ++mi)
                    ldm4(Ah[mi], st + aOff + (uint32_t)(mi*16*ROWB) + kb);
                #pragma unroll
                for (int np = 0; np < 4; ++np)
                    ldm4(Bh[np], st + bOff + (uint32_t)(np*16*ROWB) + kb);
            }
            #pragma unroll
            for (int mi = 0; mi < 2; ++mi)
                #pragma unroll
                for (int ni = 0; ni < 8; ++ni)
                    mma16816(acc[mi][ni], Ah[mi], &Bh[ni>>1][(ni&1)*2]);

            if (s + 1 < NSTAGE) {
                if (s + 3 < NSTAGE)
                    asm volatile("cp.async.wait_group 1;" ::: "memory");
                else
                    asm volatile("cp.async.wait_group 0;" ::: "memory");
                __syncthreads();
                const uint32_t sn = sb + (uint32_t)((s+1) % 3) * STAGE_B;
                #pragma unroll
                for (int mi = 0; mi < 2; ++mi)
                    ldm4(Ah[mi], sn + aOff + (uint32_t)(mi*16*ROWB));
                #pragma unroll
                for (int np = 0; np < 4; ++np)
                    ldm4(Bh[np], sn + bOff + (uint32_t)(np*16*ROWB));
                if (s + 3 < NSTAGE) load_stage(sb, s + 3, bm, bn, tid);
            }
        }

        // ---- fused epilogue: per-row partial S1,S2,S3 over this CTA's 128 cols ----
        __syncthreads();
        float* sred = (float*)sm_;             // [2 wn][128 rows][3]

        float st1[2][2] = {}, st2[2][2] = {}, st3[2][2] = {};
        #pragma unroll
        for (int ni = 0; ni < 8; ++ni) {
            const int n = bn + wn*64 + ni*8 + c2;
            const float2 bv = *(const float2*)(bias + n);
            const float2 gv = *(const float2*)(g_gw + n);
            #pragma unroll
            for (int mi = 0; mi < 2; ++mi) {
                float x0 = acc[mi][ni][0]*INV_BSCALE + bv.x;
                float x1 = acc[mi][ni][1]*INV_BSCALE + bv.y;
                float x2 = acc[mi][ni][2]*INV_BSCALE + bv.x;
                float x3 = acc[mi][ni][3]*INV_BSCALE + bv.y;
                st1[mi][0] += x0 + x1;           st1[mi][1] += x2 + x3;
                st2[mi][0] += x0*x0 + x1*x1;     st2[mi][1] += x2*x2 + x3*x3;
                st3[mi][0] += x0*gv.x + x1*gv.y; st3[mi][1] += x2*gv.x + x3*gv.y;
            }
        }
        #pragma unroll
        for (int mi = 0; mi < 2; ++mi)
            #pragma unroll
            for (int h = 0; h < 2; ++h) {
                #pragma unroll
                for (int o = 1; o < 4; o <<= 1) {
                    st1[mi][h] += __shfl_xor_sync(0xFFFFFFFFu, st1[mi][h], o);
                    st2[mi][h] += __shfl_xor_sync(0xFFFFFFFFu, st2[mi][h], o);
                    st3[mi][h] += __shfl_xor_sync(0xFFFFFFFFu, st3[mi][h], o);
                }
            }
        if ((lane & 3) == 0) {
            #pragma unroll
            for (int mi = 0; mi < 2; ++mi)
                #pragma unroll
                for (int h = 0; h < 2; ++h) {
                    const int row = wm*32 + mi*16 + h*8 + r4;
                    float* p = sred + (wn*128 + row)*3;
                    p[0] = st1[mi][h]; p[1] = st2[mi][h]; p[2] = st3[mi][h];
                }
        }
        __syncthreads();
        if (tid < 128) {
            const int m = bm + tid;
            const int t8 = tile & 7;
            #pragma unroll
            for (int c = 0; c < 3; ++c)
                g_part[(c*8 + t8)*MROWS + m] =
                    sred[(0*128 + tid)*3 + c] + sred[(1*128 + tid)*3 + c];
        }
    }
}

// ===== Kernel 4: combine partials -> g_s (125 blocks) + mask pred (block 125) =====
__global__ void combine_kernel(const float* __restrict__ mask_token)
{
    const int tid = threadIdx.x;
    if (blockIdx.x < 125) {
        const int m = blockIdx.x*128 + tid;
        float S1 = 0.f, S2 = 0.f, S3 = 0.f;
        #pragma unroll
        for (int t = 0; t < 8; ++t) {
            S1 += g_part[(0*8 + t)*MROWS + m];
            S2 += g_part[(1*8 + t)*MROWS + m];
            S3 += g_part[(2*8 + t)*MROWS + m];
        }
        const float mean = S1 * (1.0f/DIM);
        const float var  = S2 * (1.0f/DIM) - mean*mean;
        const float inv  = rsqrtf(var + LN_EPS);
        g_s[m] = inv*(S3 - mean*g_consts[0]) + g_consts[1];
    } else {
        const int lane = tid & 31, wrp = tid >> 5;
        float s1 = 0.f, s2 = 0.f, s3 = 0.f;
        #pragma unroll
        for (int i = 0; i < 8; ++i) {
            const int d = tid + i*128;
            const float x = mask_token[d];
            s1 += x; s2 += x*x; s3 += x*g_gw[d];
        }
        #pragma unroll
        for (int o = 16; o; o >>= 1) {
            s1 += __shfl_xor_sync(0xFFFFFFFFu, s1, o);
            s2 += __shfl_xor_sync(0xFFFFFFFFu, s2, o);
            s3 += __shfl_xor_sync(0xFFFFFFFFu, s3, o);
        }
        __shared__ float ws[12];
        if (lane == 0) { ws[wrp] = s1; ws[4+wrp] = s2; ws[8+wrp] = s3; }
        __syncthreads();
        if (tid == 0) {
            float S1 = ws[0]+ws[1]+ws[2]+ws[3];
            float S2 = ws[4]+ws[5]+ws[6]+ws[7];
            float S3 = ws[8]+ws[9]+ws[10]+ws[11];
            const float mean = S1 * (1.0f/DIM);
            const float var  = S2 * (1.0f/DIM) - mean*mean;
            const float inv  = rsqrtf(var + LN_EPS);
            g_s[MROWS] = inv*(S3 - mean*g_consts[0]) + g_consts[1];
        }
    }
}

// ===== Kernel 5: scatter pred/mask + loss partial, grid (8, 32) =====
__global__ void out_kernel(const float* __restrict__ expr,
                           float* __restrict__ out_pred,
                           float* __restrict__ out_mask)
{
    const int b = blockIdx.y, seg = blockIdx.x, tid = threadIdx.x;
    const float cm = g_s[MROWS];
    float part = 0.f;
    if (tid < 250) {
        const int l = seg*250 + tid;
        const int r = g_rank[b*LSEQ + l];
        const bool masked = (r >= KEEP);
        const float p = masked ? cm : g_s[b*KEEP + r];
        out_pred[b*LSEQ + l] = p;
        out_mask[b*LSEQ + l] = masked ? 1.0f : 0.0f;
        if (masked) {
            float t = expr[b*LSEQ + l];
            if (isnan(t)) t = 0.f;
            const float d = p - t;
            part = d*d;
        }
    }
    __shared__ float red[256];
    red[tid] = part; __syncthreads();
    #pragma unroll
    for (int o = 128; o > 0; o >>= 1) {
        if (tid < o) red[tid] += red[tid+o];
        __syncthreads();
    }
    if (tid == 0) g_losspart[b*8 + seg] = red[0];
}

// ===== Kernel 6: final loss =====
__global__ void loss_kernel(float* __restrict__ out)
{
    const int tid = threadIdx.x;
    __shared__ float red[256];
    red[tid] = g_losspart[tid]; __syncthreads();
    #pragma unroll
    for (int o = 128; o > 0; o >>= 1) {
        if (tid < o) red[tid] += red[tid+o];
        __syncthreads();
    }
    if (tid == 0) out[0] = red[0] / (float)NMASK;
}

// =============================== launch ===============================
extern "C" void kernel_launch(void* const* d_in, const int* in_sizes, int n_in,
                              void* d_out, int out_size)
{
    const float* expr      = (const float*)d_in[0];
    const int*   idx       = (const int*)  d_in[1];
    const float* noise     = (const float*)d_in[2];
    const float* pos_table = (const float*)d_in[3];
    const float* cls_token = (const float*)d_in[4];
    const float* w_enc     = (const float*)d_in[5];
    const float* b_enc     = (const float*)d_in[6];
    const float* gamma1    = (const float*)d_in[7];
    const float* beta1     = (const float*)d_in[8];
    const float* W_dec     = (const float*)d_in[9];
    const float* b_dec     = (const float*)d_in[10];
    const float* mask_tok  = (const float*)d_in[11];
    const float* gamma2    = (const float*)d_in[12];
    const float* beta2     = (const float*)d_in[13];
    const float* W_pred    = (const float*)d_in[14];
    const float* b_pred    = (const float*)d_in[15];

    float* out = (float*)d_out;
    float* out_loss  = out;
    float* out_pred  = out + 1;
    float* out_mask  = out + 1 + BATCH*LSEQ;
    float* out_lat0  = out + 1 + 2*BATCH*LSEQ;

    cudaFuncSetAttribute(gemm_tc_kernel,
                         cudaFuncAttributeMaxDynamicSharedMemorySize, SMEM_TOTAL);

    setup_kernel<<<1281, 256>>>(noise, W_dec, gamma2, beta2, W_pred, b_pred);
    enc_ln_kernel<<<(BATCH*(KEEP+1))/8, 256>>>(expr, idx, pos_table, cls_token,
                                               w_enc, b_enc, gamma1, beta1, out_lat0);
    gemm_tc_kernel<<<GEMM_GRID, 256, SMEM_TOTAL>>>(b_dec);
    combine_kernel<<<126, 128>>>(mask_tok);
    out_kernel<<<dim3(8, BATCH), 256>>>(expr, out_pred, out_mask);
    loss_kernel<<<1, 256>>>(out_loss);
}